// round 5
// baseline (speedup 1.0000x reference)
#include <cuda_runtime.h>

// Problem constants
#define S2       100                  // S*S
#define NCH      24                   // 3*B + C
#define NCLS     21
#define BATCHN   32768
#define NCELLS   (BATCHN * S2)        // 3,276,800
#define TILE     256                  // cells per block tile
#define NTILES   (NCELLS / TILE)      // 12800
#define GRID     1184                 // 148 SMs x 8 blocks: one persistent wave
#define SSTRIDE  257                  // padded smem stride (channel-major)

// Loss weights
#define LAMBDA_COORD 10.0
#define LAMBDA_NOOBJ 1.0
#define LAMBDA_CLASS 0.5

// log(w / SCALE) = log(w * INV_SCALE), SCALE = 6.5131/40
__device__ __constant__ float INV_SCALE = 40.0f / 6.5131f;

// Cross-block accumulators [xy, wh, obj, noobj, class], each on its own
// 128B line. Zero-initialized at module load; the finalizing block resets
// them after reading, so every launch / graph replay starts from zero.
#define ACC_STRIDE 16   // doubles per slot (128 B)
__device__ double g_acc[5 * ACC_STRIDE];     // static-init 0.0
__device__ unsigned int g_done;              // static-init 0

__device__ __forceinline__ float warp_reduce(float v) {
#pragma unroll
    for (int o = 16; o > 0; o >>= 1)
        v += __shfl_down_sync(0xffffffffu, v, o);
    return v;
}

__global__ __launch_bounds__(256)
void loss_kernel(const float4* __restrict__ pred4,   // NCELLS*6 float4
                 const float4* __restrict__ tgt4,    // NCELLS float4
                 float* __restrict__ out) {
    // channel-major staging: s[ch*SSTRIDE + cell], ch in [0,24), cell in [0,256)
    __shared__ float s[NCH * SSTRIDE];

    float lxy = 0.f, lwh = 0.f, lobj = 0.f, lnoobj = 0.f, lcls = 0.f;
    const int tid = threadIdx.x;

    for (int tile = blockIdx.x; tile < NTILES; tile += GRID) {
        // ---- coalesced target load (held in registers across syncs) ----
        const float4 t = tgt4[tile * TILE + tid];

        // ---- coalesced pred load -> smem channel-major transpose ----
        const float4* pbase = pred4 + (size_t)tile * (TILE * 6);
#pragma unroll
        for (int k = 0; k < 6; k++) {
            const int f = tid + k * TILE;          // local float4 index
            const float4 v = pbase[f];
            const int c = f / 6;                   // cell within tile
            const int j = f - 6 * c;               // float4 slot in cell
            const int ch = 4 * j;
            s[(ch + 0) * SSTRIDE + c] = v.x;
            s[(ch + 1) * SSTRIDE + c] = v.y;
            s[(ch + 2) * SSTRIDE + c] = v.z;
            s[(ch + 3) * SSTRIDE + c] = v.w;
        }
        __syncthreads();

        // ---- per-cell loss; reads conflict-free (fixed ch, lane = cell) ----
        const float conf_t = t.z;  // 0 or 1
        const float sig_conf = 1.f / (1.f + __expf(-s[2 * SSTRIDE + tid]));

        if (conf_t > 0.f) {
            const float dc = sig_conf - conf_t;
            lobj += dc * dc;

            const float sig_x = 1.f / (1.f + __expf(-s[0 * SSTRIDE + tid]));
            const float dx = sig_x - t.x;
            lxy += dx * dx;

            const float dw = s[1 * SSTRIDE + tid] - __logf(t.y * INV_SCALE);
            lwh += dw * dw;

            if (t.w > 0.f) {
                float esum = 0.f, wsum = 0.f;
#pragma unroll
                for (int c = 0; c < NCLS; c++) {
                    const float e = __expf(s[(3 + c) * SSTRIDE + tid]);
                    esum += e;
                    wsum += e * (1.0f + 0.5f * (float)c);
                }
                const float pred_mass = wsum / esum;
                const float diff = 10.f * (pred_mass + 1.f) / (t.w + 1.f) - 10.f;
                const float ad = fabsf(diff);
                lcls += (ad < 1.f) ? 0.5f * diff * diff : (ad - 0.5f);
            }
        } else {
            lnoobj += sig_conf * sig_conf;   // target conf == 0
        }
        __syncthreads();   // protect smem before next tile's stores
    }

    // ---- block reduction: warp shuffle -> smem -> warp0 -> double atomics ----
    __shared__ float r[5][8];
    const int lane = tid & 31;
    const int wid  = tid >> 5;

    lxy    = warp_reduce(lxy);
    lwh    = warp_reduce(lwh);
    lobj   = warp_reduce(lobj);
    lnoobj = warp_reduce(lnoobj);
    lcls   = warp_reduce(lcls);

    if (lane == 0) {
        r[0][wid] = lxy;  r[1][wid] = lwh;  r[2][wid] = lobj;
        r[3][wid] = lnoobj;  r[4][wid] = lcls;
    }
    __syncthreads();

    if (wid == 0) {
        float a0 = (lane < 8) ? r[0][lane] : 0.f;
        float a1 = (lane < 8) ? r[1][lane] : 0.f;
        float a2 = (lane < 8) ? r[2][lane] : 0.f;
        float a3 = (lane < 8) ? r[3][lane] : 0.f;
        float a4 = (lane < 8) ? r[4][lane] : 0.f;
        a0 = warp_reduce(a0);
        a1 = warp_reduce(a1);
        a2 = warp_reduce(a2);
        a3 = warp_reduce(a3);
        a4 = warp_reduce(a4);

        if (lane == 0) {
            atomicAdd(&g_acc[0 * ACC_STRIDE], (double)a0);
            atomicAdd(&g_acc[1 * ACC_STRIDE], (double)a1);
            atomicAdd(&g_acc[2 * ACC_STRIDE], (double)a2);
            atomicAdd(&g_acc[3 * ACC_STRIDE], (double)a3);
            atomicAdd(&g_acc[4 * ACC_STRIDE], (double)a4);

            // ---- last-block-done finalize (replaces separate kernel) ----
            __threadfence();
            const unsigned int prev = atomicAdd(&g_done, 1u);
            if (prev == GRID - 1) {
                // All other blocks' atomics are globally visible.
                // Atomic reads guarantee we see the L2-resident values.
                const double xy  = atomicAdd(&g_acc[0 * ACC_STRIDE], 0.0);
                const double wh  = atomicAdd(&g_acc[1 * ACC_STRIDE], 0.0);
                const double obj = atomicAdd(&g_acc[2 * ACC_STRIDE], 0.0);
                const double nob = atomicAdd(&g_acc[3 * ACC_STRIDE], 0.0);
                const double cls = atomicAdd(&g_acc[4 * ACC_STRIDE], 0.0);
                const double total = LAMBDA_COORD * (xy + wh) + obj
                                   + LAMBDA_NOOBJ * nob + LAMBDA_CLASS * cls;
                const double inv_bs = 1.0 / (double)BATCHN;
                out[0] = (float)(xy  * inv_bs);
                out[1] = (float)(wh  * inv_bs);
                out[2] = (float)(obj * inv_bs);
                out[3] = (float)(nob * inv_bs);
                out[4] = (float)(cls * inv_bs);
                out[5] = (float)(total * inv_bs);
                // Reset state for the next launch / graph replay.
                g_acc[0 * ACC_STRIDE] = 0.0;
                g_acc[1 * ACC_STRIDE] = 0.0;
                g_acc[2 * ACC_STRIDE] = 0.0;
                g_acc[3 * ACC_STRIDE] = 0.0;
                g_acc[4 * ACC_STRIDE] = 0.0;
                __threadfence();
                g_done = 0u;
            }
        }
    }
}

extern "C" void kernel_launch(void* const* d_in, const int* in_sizes, int n_in,
                              void* d_out, int out_size) {
    // pred is the big input (NCELLS*24 floats); target is NCELLS*4
    const float* pred = (const float*)d_in[0];
    const float* tgt  = (const float*)d_in[1];
    if (n_in >= 2 && in_sizes[0] < in_sizes[1]) {
        pred = (const float*)d_in[1];
        tgt  = (const float*)d_in[0];
    }

    loss_kernel<<<GRID, 256>>>(reinterpret_cast<const float4*>(pred),
                               reinterpret_cast<const float4*>(tgt),
                               (float*)d_out);
}

// round 7
// speedup vs baseline: 1.0873x; 1.0873x over previous
#include <cuda_runtime.h>

// Problem constants
#define S2       100                  // S*S
#define NCH      24                   // 3*B + C
#define NCLS     21
#define BATCHN   32768
#define NCELLS   (BATCHN * S2)        // 3,276,800
#define TILE     256                  // cells per block tile
#define NTILES   (NCELLS / TILE)      // 12800
#define GRID     3200                 // exactly 4 tiles/block (measured best)
#define SSTRIDE  257                  // padded smem stride (channel-major)

// Loss weights
#define LAMBDA_COORD 10.0
#define LAMBDA_NOOBJ 1.0
#define LAMBDA_CLASS 0.5

// log(w / SCALE) = log(w * INV_SCALE), SCALE = 6.5131/40
__device__ __constant__ float INV_SCALE = 40.0f / 6.5131f;

// Cross-block accumulators [xy, wh, obj, noobj, class], each on its own
// 128B line. Zero-initialized at module load; the finalizing block resets
// them after reading, so every launch / graph replay starts from zero.
#define ACC_STRIDE 16   // doubles per slot (128 B)
__device__ double g_acc[5 * ACC_STRIDE];     // static-init 0.0
__device__ unsigned int g_done;              // static-init 0

__device__ __forceinline__ float warp_reduce(float v) {
#pragma unroll
    for (int o = 16; o > 0; o >>= 1)
        v += __shfl_down_sync(0xffffffffu, v, o);
    return v;
}

__global__ __launch_bounds__(256)
void loss_kernel(const float4* __restrict__ pred4,   // NCELLS*6 float4
                 const float4* __restrict__ tgt4,    // NCELLS float4
                 float* __restrict__ out) {
    // channel-major staging: s[ch*SSTRIDE + cell], ch in [0,24), cell in [0,256)
    __shared__ float s[NCH * SSTRIDE];

    float lxy = 0.f, lwh = 0.f, lobj = 0.f, lnoobj = 0.f, lcls = 0.f;
    const int tid = threadIdx.x;

    for (int tile = blockIdx.x; tile < NTILES; tile += GRID) {
        // ---- coalesced target load (held in registers across syncs) ----
        const float4 t = tgt4[tile * TILE + tid];

        // ---- coalesced pred load -> smem channel-major transpose ----
        const float4* pbase = pred4 + (size_t)tile * (TILE * 6);
#pragma unroll
        for (int k = 0; k < 6; k++) {
            const int f = tid + k * TILE;          // local float4 index
            const float4 v = pbase[f];
            const int c = f / 6;                   // cell within tile
            const int j = f - 6 * c;               // float4 slot in cell
            const int ch = 4 * j;
            s[(ch + 0) * SSTRIDE + c] = v.x;
            s[(ch + 1) * SSTRIDE + c] = v.y;
            s[(ch + 2) * SSTRIDE + c] = v.z;
            s[(ch + 3) * SSTRIDE + c] = v.w;
        }
        __syncthreads();

        // ---- per-cell loss; reads conflict-free (fixed ch, lane = cell) ----
        const float conf_t = t.z;  // 0 or 1
        const float sig_conf = 1.f / (1.f + __expf(-s[2 * SSTRIDE + tid]));

        if (conf_t > 0.f) {
            const float dc = sig_conf - conf_t;
            lobj += dc * dc;

            const float sig_x = 1.f / (1.f + __expf(-s[0 * SSTRIDE + tid]));
            const float dx = sig_x - t.x;
            lxy += dx * dx;

            const float dw = s[1 * SSTRIDE + tid] - __logf(t.y * INV_SCALE);
            lwh += dw * dw;

            if (t.w > 0.f) {
                float esum = 0.f, wsum = 0.f;
#pragma unroll
                for (int c = 0; c < NCLS; c++) {
                    const float e = __expf(s[(3 + c) * SSTRIDE + tid]);
                    esum += e;
                    wsum += e * (1.0f + 0.5f * (float)c);
                }
                const float pred_mass = wsum / esum;
                const float diff = 10.f * (pred_mass + 1.f) / (t.w + 1.f) - 10.f;
                const float ad = fabsf(diff);
                lcls += (ad < 1.f) ? 0.5f * diff * diff : (ad - 0.5f);
            }
        } else {
            lnoobj += sig_conf * sig_conf;   // target conf == 0
        }
        __syncthreads();   // protect smem before next tile's stores
    }

    // ---- block reduction: warp shuffle -> smem -> warp0 -> double atomics ----
    __shared__ float r[5][8];
    const int lane = tid & 31;
    const int wid  = tid >> 5;

    lxy    = warp_reduce(lxy);
    lwh    = warp_reduce(lwh);
    lobj   = warp_reduce(lobj);
    lnoobj = warp_reduce(lnoobj);
    lcls   = warp_reduce(lcls);

    if (lane == 0) {
        r[0][wid] = lxy;  r[1][wid] = lwh;  r[2][wid] = lobj;
        r[3][wid] = lnoobj;  r[4][wid] = lcls;
    }
    __syncthreads();

    if (wid == 0) {
        float a0 = (lane < 8) ? r[0][lane] : 0.f;
        float a1 = (lane < 8) ? r[1][lane] : 0.f;
        float a2 = (lane < 8) ? r[2][lane] : 0.f;
        float a3 = (lane < 8) ? r[3][lane] : 0.f;
        float a4 = (lane < 8) ? r[4][lane] : 0.f;
        a0 = warp_reduce(a0);
        a1 = warp_reduce(a1);
        a2 = warp_reduce(a2);
        a3 = warp_reduce(a3);
        a4 = warp_reduce(a4);

        if (lane == 0) {
            atomicAdd(&g_acc[0 * ACC_STRIDE], (double)a0);
            atomicAdd(&g_acc[1 * ACC_STRIDE], (double)a1);
            atomicAdd(&g_acc[2 * ACC_STRIDE], (double)a2);
            atomicAdd(&g_acc[3 * ACC_STRIDE], (double)a3);
            atomicAdd(&g_acc[4 * ACC_STRIDE], (double)a4);

            // ---- last-block-done finalize (replaces separate kernel) ----
            __threadfence();
            const unsigned int prev = atomicAdd(&g_done, 1u);
            if (prev == GRID - 1) {
                // All other blocks' atomics are globally visible.
                const double xy  = atomicAdd(&g_acc[0 * ACC_STRIDE], 0.0);
                const double wh  = atomicAdd(&g_acc[1 * ACC_STRIDE], 0.0);
                const double obj = atomicAdd(&g_acc[2 * ACC_STRIDE], 0.0);
                const double nob = atomicAdd(&g_acc[3 * ACC_STRIDE], 0.0);
                const double cls = atomicAdd(&g_acc[4 * ACC_STRIDE], 0.0);
                const double total = LAMBDA_COORD * (xy + wh) + obj
                                   + LAMBDA_NOOBJ * nob + LAMBDA_CLASS * cls;
                const double inv_bs = 1.0 / (double)BATCHN;
                out[0] = (float)(xy  * inv_bs);
                out[1] = (float)(wh  * inv_bs);
                out[2] = (float)(obj * inv_bs);
                out[3] = (float)(nob * inv_bs);
                out[4] = (float)(cls * inv_bs);
                out[5] = (float)(total * inv_bs);
                // Reset state for the next launch / graph replay.
                g_acc[0 * ACC_STRIDE] = 0.0;
                g_acc[1 * ACC_STRIDE] = 0.0;
                g_acc[2 * ACC_STRIDE] = 0.0;
                g_acc[3 * ACC_STRIDE] = 0.0;
                g_acc[4 * ACC_STRIDE] = 0.0;
                __threadfence();
                g_done = 0u;
            }
        }
    }
}

extern "C" void kernel_launch(void* const* d_in, const int* in_sizes, int n_in,
                              void* d_out, int out_size) {
    // pred is the big input (NCELLS*24 floats); target is NCELLS*4
    const float* pred = (const float*)d_in[0];
    const float* tgt  = (const float*)d_in[1];
    if (n_in >= 2 && in_sizes[0] < in_sizes[1]) {
        pred = (const float*)d_in[1];
        tgt  = (const float*)d_in[0];
    }

    loss_kernel<<<GRID, 256>>>(reinterpret_cast<const float4*>(pred),
                               reinterpret_cast<const float4*>(tgt),
                               (float*)d_out);
}

// round 8
// speedup vs baseline: 1.1275x; 1.0370x over previous
#include <cuda_runtime.h>

// Problem constants
#define S2       100                  // S*S
#define NCH      24                   // 3*B + C
#define NCLS     21
#define BATCHN   32768
#define NCELLS   (BATCHN * S2)        // 3,276,800
#define TILE     256                  // cells per block tile
#define NTILES   (NCELLS / TILE)      // 12800
#define GRID     3200                 // exactly 4 tiles/block (measured best)
#define TPB      (NTILES / GRID)      // 4 tiles per block
#define SSTRIDE  257                  // padded smem stride (channel-major)

// Loss weights
#define LAMBDA_COORD 10.0
#define LAMBDA_NOOBJ 1.0
#define LAMBDA_CLASS 0.5

// log(w / SCALE) = log(w * INV_SCALE), SCALE = 6.5131/40
__device__ __constant__ float INV_SCALE = 40.0f / 6.5131f;

// Cross-block accumulators [xy, wh, obj, noobj, class], each on its own
// 128B line. Zero-initialized at module load; the finalizing block resets
// them after reading, so every launch / graph replay starts from zero.
#define ACC_STRIDE 16   // doubles per slot (128 B)
__device__ double g_acc[5 * ACC_STRIDE];     // static-init 0.0
__device__ unsigned int g_done;              // static-init 0

__device__ __forceinline__ float warp_reduce(float v) {
#pragma unroll
    for (int o = 16; o > 0; o >>= 1)
        v += __shfl_down_sync(0xffffffffu, v, o);
    return v;
}

__global__ __launch_bounds__(256, 4)
void loss_kernel(const float4* __restrict__ pred4,   // NCELLS*6 float4
                 const float4* __restrict__ tgt4,    // NCELLS float4
                 float* __restrict__ out) {
    // channel-major staging: s[ch*SSTRIDE + cell], ch in [0,24), cell in [0,256)
    __shared__ float s[NCH * SSTRIDE];

    float lxy = 0.f, lwh = 0.f, lobj = 0.f, lnoobj = 0.f, lcls = 0.f;
    const int tid = threadIdx.x;

    // ---- prefetch tile 0 into registers ----
    int tile = blockIdx.x;
    float4 t = tgt4[tile * TILE + tid];
    float4 v[6];
    {
        const float4* pb = pred4 + (size_t)tile * (TILE * 6);
#pragma unroll
        for (int k = 0; k < 6; k++) v[k] = pb[tid + k * TILE];
    }

#pragma unroll 1
    for (int it = 0; it < TPB; it++) {
        // ---- store prefetched tile to smem (channel-major transpose) ----
#pragma unroll
        for (int k = 0; k < 6; k++) {
            const int f = tid + k * TILE;          // local float4 index
            const int c = f / 6;                   // cell within tile
            const int j = f - 6 * c;               // float4 slot in cell
            const int ch = 4 * j;
            s[(ch + 0) * SSTRIDE + c] = v[k].x;
            s[(ch + 1) * SSTRIDE + c] = v[k].y;
            s[(ch + 2) * SSTRIDE + c] = v[k].z;
            s[(ch + 3) * SSTRIDE + c] = v[k].w;
        }
        const float4 tc = t;   // current tile's target (this thread's cell)
        __syncthreads();

        // ---- issue next tile's loads NOW; they fly during compute ----
        const int ntile = tile + GRID;
        if (it + 1 < TPB) {
            t = tgt4[ntile * TILE + tid];
            const float4* pb = pred4 + (size_t)ntile * (TILE * 6);
#pragma unroll
            for (int k = 0; k < 6; k++) v[k] = pb[tid + k * TILE];
        }
        tile = ntile;

        // ---- per-cell loss; reads conflict-free (fixed ch, lane = cell) ----
        const float conf_t = tc.z;  // 0 or 1
        const float sig_conf = 1.f / (1.f + __expf(-s[2 * SSTRIDE + tid]));

        if (conf_t > 0.f) {
            const float dc = sig_conf - conf_t;
            lobj += dc * dc;

            const float sig_x = 1.f / (1.f + __expf(-s[0 * SSTRIDE + tid]));
            const float dx = sig_x - tc.x;
            lxy += dx * dx;

            const float dw = s[1 * SSTRIDE + tid] - __logf(tc.y * INV_SCALE);
            lwh += dw * dw;

            if (tc.w > 0.f) {
                float esum = 0.f, wsum = 0.f;
#pragma unroll
                for (int c = 0; c < NCLS; c++) {
                    const float e = __expf(s[(3 + c) * SSTRIDE + tid]);
                    esum += e;
                    wsum += e * (1.0f + 0.5f * (float)c);
                }
                const float pred_mass = wsum / esum;
                const float diff = 10.f * (pred_mass + 1.f) / (tc.w + 1.f) - 10.f;
                const float ad = fabsf(diff);
                lcls += (ad < 1.f) ? 0.5f * diff * diff : (ad - 0.5f);
            }
        } else {
            lnoobj += sig_conf * sig_conf;   // target conf == 0
        }
        __syncthreads();   // smem consumed; next iteration may overwrite
    }

    // ---- block reduction: warp shuffle -> smem -> warp0 -> double atomics ----
    __shared__ float r[5][8];
    const int lane = tid & 31;
    const int wid  = tid >> 5;

    lxy    = warp_reduce(lxy);
    lwh    = warp_reduce(lwh);
    lobj   = warp_reduce(lobj);
    lnoobj = warp_reduce(lnoobj);
    lcls   = warp_reduce(lcls);

    if (lane == 0) {
        r[0][wid] = lxy;  r[1][wid] = lwh;  r[2][wid] = lobj;
        r[3][wid] = lnoobj;  r[4][wid] = lcls;
    }
    __syncthreads();

    if (wid == 0) {
        float a0 = (lane < 8) ? r[0][lane] : 0.f;
        float a1 = (lane < 8) ? r[1][lane] : 0.f;
        float a2 = (lane < 8) ? r[2][lane] : 0.f;
        float a3 = (lane < 8) ? r[3][lane] : 0.f;
        float a4 = (lane < 8) ? r[4][lane] : 0.f;
        a0 = warp_reduce(a0);
        a1 = warp_reduce(a1);
        a2 = warp_reduce(a2);
        a3 = warp_reduce(a3);
        a4 = warp_reduce(a4);

        if (lane == 0) {
            atomicAdd(&g_acc[0 * ACC_STRIDE], (double)a0);
            atomicAdd(&g_acc[1 * ACC_STRIDE], (double)a1);
            atomicAdd(&g_acc[2 * ACC_STRIDE], (double)a2);
            atomicAdd(&g_acc[3 * ACC_STRIDE], (double)a3);
            atomicAdd(&g_acc[4 * ACC_STRIDE], (double)a4);

            // ---- last-block-done finalize ----
            __threadfence();
            const unsigned int prev = atomicAdd(&g_done, 1u);
            if (prev == GRID - 1) {
                const double xy  = atomicAdd(&g_acc[0 * ACC_STRIDE], 0.0);
                const double wh  = atomicAdd(&g_acc[1 * ACC_STRIDE], 0.0);
                const double obj = atomicAdd(&g_acc[2 * ACC_STRIDE], 0.0);
                const double nob = atomicAdd(&g_acc[3 * ACC_STRIDE], 0.0);
                const double cls = atomicAdd(&g_acc[4 * ACC_STRIDE], 0.0);
                const double total = LAMBDA_COORD * (xy + wh) + obj
                                   + LAMBDA_NOOBJ * nob + LAMBDA_CLASS * cls;
                const double inv_bs = 1.0 / (double)BATCHN;
                out[0] = (float)(xy  * inv_bs);
                out[1] = (float)(wh  * inv_bs);
                out[2] = (float)(obj * inv_bs);
                out[3] = (float)(nob * inv_bs);
                out[4] = (float)(cls * inv_bs);
                out[5] = (float)(total * inv_bs);
                // Reset state for the next launch / graph replay.
                g_acc[0 * ACC_STRIDE] = 0.0;
                g_acc[1 * ACC_STRIDE] = 0.0;
                g_acc[2 * ACC_STRIDE] = 0.0;
                g_acc[3 * ACC_STRIDE] = 0.0;
                g_acc[4 * ACC_STRIDE] = 0.0;
                __threadfence();
                g_done = 0u;
            }
        }
    }
}

extern "C" void kernel_launch(void* const* d_in, const int* in_sizes, int n_in,
                              void* d_out, int out_size) {
    // pred is the big input (NCELLS*24 floats); target is NCELLS*4
    const float* pred = (const float*)d_in[0];
    const float* tgt  = (const float*)d_in[1];
    if (n_in >= 2 && in_sizes[0] < in_sizes[1]) {
        pred = (const float*)d_in[1];
        tgt  = (const float*)d_in[0];
    }

    loss_kernel<<<GRID, 256>>>(reinterpret_cast<const float4*>(pred),
                               reinterpret_cast<const float4*>(tgt),
                               (float*)d_out);
}

// round 10
// speedup vs baseline: 1.1281x; 1.0005x over previous
#include <cuda_runtime.h>

// Problem constants
#define S2       100                   // S*S
#define NCH      24                    // 3*B + C
#define NCLS     21
#define BATCHN   32768
#define NCELLS   (BATCHN * S2)         // 3,276,800
#define GRID     3200
#define WPB      8                     // warps per block
#define WARPS_TOTAL (GRID * WPB)       // 25600
#define NCHUNKS  (NCELLS / 32)         // 102,400 (32 cells per warp-chunk)
#define CPW      (NCHUNKS / WARPS_TOTAL) // 4 chunks per warp
#define WSTRIDE  33                    // per-warp smem row stride (floats)
#define WSLICE   (NCH * WSTRIDE)       // 792 floats per warp slice

// Loss weights
#define LAMBDA_COORD 10.0
#define LAMBDA_NOOBJ 1.0
#define LAMBDA_CLASS 0.5

// log(w / SCALE) = log(w * INV_SCALE), SCALE = 6.5131/40
__device__ __constant__ float INV_SCALE = 40.0f / 6.5131f;

// Cross-block accumulators [xy, wh, obj, noobj, class], each on its own
// 128B line. Zero-initialized at module load; the finalizing block resets
// them after reading, so every launch / graph replay starts from zero.
#define ACC_STRIDE 16   // doubles per slot (128 B)
__device__ double g_acc[5 * ACC_STRIDE];     // static-init 0.0
__device__ unsigned int g_done;              // static-init 0

__device__ __forceinline__ float warp_reduce(float v) {
#pragma unroll
    for (int o = 16; o > 0; o >>= 1)
        v += __shfl_down_sync(0xffffffffu, v, o);
    return v;
}

__global__ __launch_bounds__(256, 4)
void loss_kernel(const float4* __restrict__ pred4,   // NCELLS*6 float4
                 const float4* __restrict__ tgt4,    // NCELLS float4
                 float* __restrict__ out) {
    // Per-warp private staging slices: no block-wide barriers in the mainloop.
    __shared__ float s[WPB * WSLICE];

    const int tid  = threadIdx.x;
    const int lane = tid & 31;
    const int wid  = tid >> 5;
    float* ss = &s[wid * WSLICE];     // this warp's slice, stride WSTRIDE

    float lxy = 0.f, lwh = 0.f, lobj = 0.f, lnoobj = 0.f, lcls = 0.f;

    // ---- prefetch chunk 0 (32 cells) into registers ----
    int chunk = blockIdx.x * WPB + wid;
    float4 t = tgt4[chunk * 32 + lane];
    float4 v[6];
    {
        const float4* pb = pred4 + (size_t)chunk * (32 * 6);
#pragma unroll
        for (int k = 0; k < 6; k++) v[k] = pb[lane + k * 32];
    }

#pragma unroll 1
    for (int it = 0; it < CPW; it++) {
        // ---- store prefetched chunk to warp slice (channel-major) ----
#pragma unroll
        for (int k = 0; k < 6; k++) {
            const int f = lane + k * 32;           // local float4 index
            const int c = f / 6;                   // cell within chunk [0,32)
            const int j = f - 6 * c;               // float4 slot in cell
            const int ch = 4 * j;
            ss[(ch + 0) * WSTRIDE + c] = v[k].x;
            ss[(ch + 1) * WSTRIDE + c] = v[k].y;
            ss[(ch + 2) * WSTRIDE + c] = v[k].z;
            ss[(ch + 3) * WSTRIDE + c] = v[k].w;
        }
        const float4 tc = t;   // current chunk's target (this lane's cell)
        __syncwarp();

        // ---- issue next chunk's loads NOW; they fly during compute ----
        const int nchunk = chunk + WARPS_TOTAL;
        if (it + 1 < CPW) {
            t = tgt4[nchunk * 32 + lane];
            const float4* pb = pred4 + (size_t)nchunk * (32 * 6);
#pragma unroll
            for (int k = 0; k < 6; k++) v[k] = pb[lane + k * 32];
        }
        chunk = nchunk;

        // ---- per-cell loss; slice reads conflict-free (stride 33) ----
        const float conf_t = tc.z;  // 0 or 1
        const float sig_conf = 1.f / (1.f + __expf(-ss[2 * WSTRIDE + lane]));

        if (conf_t > 0.f) {
            const float dc = sig_conf - conf_t;
            lobj += dc * dc;

            const float sig_x = 1.f / (1.f + __expf(-ss[0 * WSTRIDE + lane]));
            const float dx = sig_x - tc.x;
            lxy += dx * dx;

            const float dw = ss[1 * WSTRIDE + lane] - __logf(tc.y * INV_SCALE);
            lwh += dw * dw;

            if (tc.w > 0.f) {
                float esum = 0.f, wsum = 0.f;
#pragma unroll
                for (int c = 0; c < NCLS; c++) {
                    const float e = __expf(ss[(3 + c) * WSTRIDE + lane]);
                    esum += e;
                    wsum += e * (1.0f + 0.5f * (float)c);
                }
                const float pred_mass = wsum / esum;
                const float diff = 10.f * (pred_mass + 1.f) / (tc.w + 1.f) - 10.f;
                const float ad = fabsf(diff);
                lcls += (ad < 1.f) ? 0.5f * diff * diff : (ad - 0.5f);
            }
        } else {
            lnoobj += sig_conf * sig_conf;   // target conf == 0
        }
        __syncwarp();   // slice consumed; next iteration overwrites
    }

    // ---- block reduction: warp shuffle -> smem -> warp0 -> double atomics ----
    __shared__ float r[5][WPB];

    lxy    = warp_reduce(lxy);
    lwh    = warp_reduce(lwh);
    lobj   = warp_reduce(lobj);
    lnoobj = warp_reduce(lnoobj);
    lcls   = warp_reduce(lcls);

    if (lane == 0) {
        r[0][wid] = lxy;  r[1][wid] = lwh;  r[2][wid] = lobj;
        r[3][wid] = lnoobj;  r[4][wid] = lcls;
    }
    __syncthreads();

    if (wid == 0) {
        float a0 = (lane < WPB) ? r[0][lane] : 0.f;
        float a1 = (lane < WPB) ? r[1][lane] : 0.f;
        float a2 = (lane < WPB) ? r[2][lane] : 0.f;
        float a3 = (lane < WPB) ? r[3][lane] : 0.f;
        float a4 = (lane < WPB) ? r[4][lane] : 0.f;
        a0 = warp_reduce(a0);
        a1 = warp_reduce(a1);
        a2 = warp_reduce(a2);
        a3 = warp_reduce(a3);
        a4 = warp_reduce(a4);

        if (lane == 0) {
            atomicAdd(&g_acc[0 * ACC_STRIDE], (double)a0);
            atomicAdd(&g_acc[1 * ACC_STRIDE], (double)a1);
            atomicAdd(&g_acc[2 * ACC_STRIDE], (double)a2);
            atomicAdd(&g_acc[3 * ACC_STRIDE], (double)a3);
            atomicAdd(&g_acc[4 * ACC_STRIDE], (double)a4);

            // ---- last-block-done finalize ----
            __threadfence();
            const unsigned int prev = atomicAdd(&g_done, 1u);
            if (prev == GRID - 1) {
                const double xy  = atomicAdd(&g_acc[0 * ACC_STRIDE], 0.0);
                const double wh  = atomicAdd(&g_acc[1 * ACC_STRIDE], 0.0);
                const double obj = atomicAdd(&g_acc[2 * ACC_STRIDE], 0.0);
                const double nob = atomicAdd(&g_acc[3 * ACC_STRIDE], 0.0);
                const double cls = atomicAdd(&g_acc[4 * ACC_STRIDE], 0.0);
                const double total = LAMBDA_COORD * (xy + wh) + obj
                                   + LAMBDA_NOOBJ * nob + LAMBDA_CLASS * cls;
                const double inv_bs = 1.0 / (double)BATCHN;
                out[0] = (float)(xy  * inv_bs);
                out[1] = (float)(wh  * inv_bs);
                out[2] = (float)(obj * inv_bs);
                out[3] = (float)(nob * inv_bs);
                out[4] = (float)(cls * inv_bs);
                out[5] = (float)(total * inv_bs);
                // Reset state for the next launch / graph replay.
                g_acc[0 * ACC_STRIDE] = 0.0;
                g_acc[1 * ACC_STRIDE] = 0.0;
                g_acc[2 * ACC_STRIDE] = 0.0;
                g_acc[3 * ACC_STRIDE] = 0.0;
                g_acc[4 * ACC_STRIDE] = 0.0;
                __threadfence();
                g_done = 0u;
            }
        }
    }
}

extern "C" void kernel_launch(void* const* d_in, const int* in_sizes, int n_in,
                              void* d_out, int out_size) {
    // pred is the big input (NCELLS*24 floats); target is NCELLS*4
    const float* pred = (const float*)d_in[0];
    const float* tgt  = (const float*)d_in[1];
    if (n_in >= 2 && in_sizes[0] < in_sizes[1]) {
        pred = (const float*)d_in[1];
        tgt  = (const float*)d_in[0];
    }

    loss_kernel<<<GRID, 256>>>(reinterpret_cast<const float4*>(pred),
                               reinterpret_cast<const float4*>(tgt),
                               (float*)d_out);
}